// round 13
// baseline (speedup 1.0000x reference)
#include <cuda_runtime.h>
#include <math.h>
#include <stdint.h>

#define TT 2048
#define BB 64
#define KIN 256
#define HH 256

typedef unsigned long long ull;

// Scratch for precomputed input projection xp[t][b][h] (134 MB device global).
__device__ float g_xp[(size_t)TT * BB * HH];

// ---------------------------------------------------------------------------
// f32x2 helpers (Blackwell packed fp32 pipe)
// ---------------------------------------------------------------------------
__device__ __forceinline__ ull ffma2(ull a, ull b, ull c) {
    ull d;
    asm("fma.rn.f32x2 %0, %1, %2, %3;" : "=l"(d) : "l"(a), "l"(b), "l"(c));
    return d;
}
__device__ __forceinline__ ull fadd2(ull a, ull b) {
    ull d;
    asm("add.rn.f32x2 %0, %1, %2;" : "=l"(d) : "l"(a), "l"(b));
    return d;
}
__device__ __forceinline__ ull fdup2(float a) {
    ull d; unsigned u = __float_as_uint(a);
    asm("mov.b64 %0, {%1, %2};" : "=l"(d) : "r"(u), "r"(u));
    return d;
}
__device__ __forceinline__ ull fpack2(float a, float b) {
    ull d;
    asm("mov.b64 %0, {%1, %2};" : "=l"(d)
        : "r"(__float_as_uint(a)), "r"(__float_as_uint(b)));
    return d;
}
__device__ __forceinline__ float2 funpack2(ull a) {
    unsigned lo, hi;
    asm("mov.b64 {%0, %1}, %2;" : "=r"(lo), "=r"(hi) : "l"(a));
    return make_float2(__uint_as_float(lo), __uint_as_float(hi));
}
__device__ __forceinline__ uint32_t smem_u32(const void* p) {
    uint32_t a;
    asm("{ .reg .u64 t; cvta.to.shared.u64 t, %1; cvt.u32.u64 %0, t; }"
        : "=r"(a) : "l"(p));
    return a;
}
__device__ __forceinline__ uint32_t mapa_peer(uint32_t local, uint32_t peer) {
    uint32_t r;
    asm("mapa.shared::cluster.u32 %0, %1, %2;" : "=r"(r) : "r"(local), "r"(peer));
    return r;
}
__device__ __forceinline__ void st_async_b64(uint32_t raddr, ull v, uint32_t rbar) {
    asm volatile(
        "st.async.shared::cluster.mbarrier::complete_tx::bytes.b64 [%0], %1, [%2];"
        :: "r"(raddr), "l"(v), "r"(rbar) : "memory");
}
__device__ __forceinline__ void mbar_init(uint32_t addr, uint32_t cnt) {
    asm volatile("mbarrier.init.shared.b64 [%0], %1;" :: "r"(addr), "r"(cnt) : "memory");
}
__device__ __forceinline__ void mbar_expect_tx(uint32_t addr, uint32_t bytes) {
    asm volatile("mbarrier.arrive.expect_tx.shared.b64 _, [%0], %1;"
                 :: "r"(addr), "r"(bytes) : "memory");
}
__device__ __forceinline__ void mbar_wait_parity(uint32_t addr, uint32_t parity) {
    asm volatile(
        "{\n\t"
        ".reg .pred P;\n\t"
        "WL_%=:\n\t"
        "mbarrier.try_wait.parity.acquire.cluster.shared::cta.b64 P, [%0], %1, 0x989680;\n\t"
        "@!P bra WL_%=;\n\t"
        "}" :: "r"(addr), "r"(parity) : "memory");
}
#define CLUSTER_SYNC_() do { \
    asm volatile("barrier.cluster.arrive.aligned;" ::: "memory"); \
    asm volatile("barrier.cluster.wait.aligned;" ::: "memory"); \
} while (0)

// ---------------------------------------------------------------------------
// Kernel 1: xp[m][n] = x[m][:] . W_ih[n][:] + b_ih[n] + b_hh[n]   (f32x2 GEMM)
// (unchanged: proven)
// ---------------------------------------------------------------------------
__global__ __launch_bounds__(256, 2) void xp_gemm_kernel(
    const float* __restrict__ x,
    const float* __restrict__ Wih,
    const float* __restrict__ b_ih,
    const float* __restrict__ b_hh)
{
    __shared__ __align__(16) float As[16][132];
    __shared__ __align__(16) float Bs[16][132];

    const int tid = threadIdx.x;
    const int m0 = blockIdx.x * 128;
    const int n0 = blockIdx.y * 128;
    const int ty = tid >> 4;
    const int tx = tid & 15;

    ull acc[8][4];
#pragma unroll
    for (int i = 0; i < 8; i++)
#pragma unroll
        for (int p = 0; p < 4; p++) acc[i][p] = 0ull;

    for (int kt = 0; kt < KIN; kt += 16) {
#pragma unroll
        for (int l = 0; l < 2; l++) {
            int id  = tid + l * 256;
            int row = id >> 2;
            int c4  = (id & 3) * 4;
            float4 av = *(const float4*)(x   + (size_t)(m0 + row) * KIN + kt + c4);
            As[c4 + 0][row] = av.x; As[c4 + 1][row] = av.y;
            As[c4 + 2][row] = av.z; As[c4 + 3][row] = av.w;
            float4 bv = *(const float4*)(Wih + (size_t)(n0 + row) * KIN + kt + c4);
            Bs[c4 + 0][row] = bv.x; Bs[c4 + 1][row] = bv.y;
            Bs[c4 + 2][row] = bv.z; Bs[c4 + 3][row] = bv.w;
        }
        __syncthreads();

#pragma unroll
        for (int k = 0; k < 16; k++) {
            float4 a03 = *(const float4*)&As[k][ty * 8];
            float4 a47 = *(const float4*)&As[k][ty * 8 + 4];
            ulonglong2 bq0 = *(const ulonglong2*)&Bs[k][tx * 8];
            ulonglong2 bq1 = *(const ulonglong2*)&Bs[k][tx * 8 + 4];
            ull bp[4] = { bq0.x, bq0.y, bq1.x, bq1.y };
            float av[8] = { a03.x, a03.y, a03.z, a03.w, a47.x, a47.y, a47.z, a47.w };
#pragma unroll
            for (int i = 0; i < 8; i++) {
                ull ad = fdup2(av[i]);
#pragma unroll
                for (int p = 0; p < 4; p++)
                    acc[i][p] = ffma2(ad, bp[p], acc[i][p]);
            }
        }
        __syncthreads();
    }

    float bb[8];
#pragma unroll
    for (int j = 0; j < 8; j++) {
        int n = n0 + tx * 8 + j;
        bb[j] = b_ih[n] + b_hh[n];
    }
#pragma unroll
    for (int i = 0; i < 8; i++) {
        float* dst = g_xp + (size_t)(m0 + ty * 8 + i) * HH + n0 + tx * 8;
        float2 c0 = funpack2(acc[i][0]);
        float2 c1 = funpack2(acc[i][1]);
        float2 c2 = funpack2(acc[i][2]);
        float2 c3 = funpack2(acc[i][3]);
        float4 v0 = make_float4(c0.x + bb[0], c0.y + bb[1], c1.x + bb[2], c1.y + bb[3]);
        float4 v1 = make_float4(c2.x + bb[4], c2.y + bb[5], c3.x + bb[6], c3.y + bb[7]);
        *(float4*)dst       = v0;
        *(float4*)(dst + 4) = v1;
    }
}

// ---------------------------------------------------------------------------
// Kernel 2: serial recurrence, partial-sum exchange, TWO BATCHES PER CLUSTER.
// Grid = 64 CTAs = 32 clusters x 2. Cluster cid owns batches 2cid, 2cid+1.
// W_hh is batch-independent -> same 32 ull register W serves both batches.
// Per pair-step: compute+send batch-A partials, compute+send batch-B
// partials (B's compute hides A's DSMEM flight), then receivers
// wait A -> tanh A -> wait B -> tanh B -> one __syncthreads.
// Each batch runs the PROVEN independent protocol: 64 x 8 B st.async,
// two mbarriers alternated by t&1, phase (t>>1)&1, double-buffered
// rsm + local h half. Senders = high warps 8-15 (arbiter priority).
// h chunks padded to stride 36 -> conflict-free LDS.128.
// ---------------------------------------------------------------------------
#define HP   36                       // padded chunk stride (floats)
#define HBUF (4 * HP)                 // 144 floats per local-h buffer
#define RBUF 128                      // recv partials per buffer

__global__ __launch_bounds__(512, 1) __cluster_dims__(2, 1, 1)
void rnn_scan_kernel(const float* __restrict__ Whh, float* __restrict__ out)
{
    __shared__ __align__(16) float hsm[2][2][HBUF];  // [batch][par][.]
    __shared__ __align__(16) float rsm[2][2][RBUF];  // [batch][par][.]
    __shared__ __align__(8)  ull   mbars[2][2];      // [batch][par]

    const int tid = threadIdx.x;
    const unsigned rank = blockIdx.x & 1u;
    const int cid = blockIdx.x >> 1;             // cluster id: batches 2cid, 2cid+1
    const int c  = tid & 3;                      // K sub-chunk / role lane
    const int gg = (tid >> 2) & 63;              // row-pair index within half
    const bool sender = (tid >= 256);            // warps 8-15: compute peer rows
    const int half_base = sender ? (int)((rank ^ 1u) * 128) : (int)(rank * 128);
    const int r0 = half_base + 2 * gg;           // target rows r0, r0+1
    const int k0 = (int)rank * 128 + 32 * c;     // own-K chunk

    const uint32_t mb_base  = smem_u32(&mbars[0][0]);
    const uint32_t rsm_base = smem_u32(&rsm[0][0][0]);
    const uint32_t peer = rank ^ 1u;
    const uint32_t peer_mb_base  = mapa_peer(mb_base, peer);
    const uint32_t peer_rsm_base = mapa_peer(rsm_base, peer);

    // Register-resident W: rows r0, r0+1 x K-chunk [k0, k0+32) as f32x2 pairs.
    ull w0[16], w1[16];
    {
        const ull* p0 = (const ull*)(Whh + (size_t)r0 * HH + k0);
        const ull* p1 = (const ull*)(Whh + (size_t)(r0 + 1) * HH + k0);
#pragma unroll
        for (int i = 0; i < 16; i++) { w0[i] = p0[i]; w1[i] = p1[i]; }
    }

    if (tid < HBUF) { hsm[0][0][tid] = 0.0f; hsm[1][0][tid] = 0.0f; }
    if (tid == 0) {
        mbar_init(mb_base + 0,  1);   // mbars[0][0]
        mbar_init(mb_base + 8,  1);   // mbars[0][1]
        mbar_init(mb_base + 16, 1);   // mbars[1][0]
        mbar_init(mb_base + 24, 1);   // mbars[1][1]
    }
    __syncthreads();
    CLUSTER_SYNC_();                              // peer mbars visible

    const size_t tstride = (size_t)BB * HH;
    // Receiver per-lane scalar row (c < 2): row r0 + c, per batch.
    const float* xppA  = g_xp + (size_t)(2 * cid)     * HH + r0 + c;
    const float* xppB  = g_xp + (size_t)(2 * cid + 1) * HH + r0 + c;
    float*       outpA = out  + (size_t)(2 * cid)     * HH + r0 + c;
    float*       outpB = out  + (size_t)(2 * cid + 1) * HH + r0 + c;

    float xvA = 0.0f, xvB = 0.0f;
    if (!sender && c < 2) { xvA = *xppA; xvB = *xppB; }   // xp for t = 0

    for (int t = 0; t < TT; t++) {
        const unsigned par = (unsigned)t & 1u;
        const unsigned phase = ((unsigned)t >> 1) & 1u;
        const uint32_t mbA      = mb_base + par * 8u;            // mbars[0][par]
        const uint32_t mbB      = mb_base + 16u + par * 8u;      // mbars[1][par]
        const uint32_t peer_mbA = peer_mb_base + par * 8u;
        const uint32_t peer_mbB = peer_mb_base + 16u + par * 8u;

        if (tid == 0) { mbar_expect_tx(mbA, 512); mbar_expect_tx(mbB, 512); }

        // ================= batch A: partials over own-K chunk =================
        float s0A, s1A;
        {
            const ulonglong2* hp = (const ulonglong2*)&hsm[0][par][HP * c];
            ull a0A = 0ull, a1A = 0ull, a0B = 0ull, a1B = 0ull;
#pragma unroll
            for (int i = 0; i < 4; i++) {
                ulonglong2 hq = hp[i];
                a0A = ffma2(w0[2 * i],     hq.x, a0A);
                a1A = ffma2(w1[2 * i],     hq.x, a1A);
                a0A = ffma2(w0[2 * i + 1], hq.y, a0A);
                a1A = ffma2(w1[2 * i + 1], hq.y, a1A);
            }
#pragma unroll
            for (int i = 4; i < 8; i++) {
                ulonglong2 hq = hp[i];
                a0B = ffma2(w0[2 * i],     hq.x, a0B);
                a1B = ffma2(w1[2 * i],     hq.x, a1B);
                a0B = ffma2(w0[2 * i + 1], hq.y, a0B);
                a1B = ffma2(w1[2 * i + 1], hq.y, a1B);
            }
            float2 u0 = funpack2(fadd2(a0A, a0B));
            float2 u1 = funpack2(fadd2(a1A, a1B));
            s0A = u0.x + u0.y;
            s1A = u1.x + u1.y;
#pragma unroll
            for (int m = 1; m < 4; m <<= 1) {
                s0A += __shfl_xor_sync(0xffffffffu, s0A, m);
                s1A += __shfl_xor_sync(0xffffffffu, s1A, m);
            }
        }
        if (sender && c == 0) {       // send A early; flight hidden by batch B
            uint32_t raddr = peer_rsm_base + (par * (unsigned)RBUF + 2u * (unsigned)gg) * 4u;
            st_async_b64(raddr, fpack2(s0A, s1A), peer_mbA);
        }

        // ================= batch B: partials over own-K chunk =================
        float s0B, s1B;
        {
            const ulonglong2* hp = (const ulonglong2*)&hsm[1][par][HP * c];
            ull a0A = 0ull, a1A = 0ull, a0B = 0ull, a1B = 0ull;
#pragma unroll
            for (int i = 0; i < 4; i++) {
                ulonglong2 hq = hp[i];
                a0A = ffma2(w0[2 * i],     hq.x, a0A);
                a1A = ffma2(w1[2 * i],     hq.x, a1A);
                a0A = ffma2(w0[2 * i + 1], hq.y, a0A);
                a1A = ffma2(w1[2 * i + 1], hq.y, a1A);
            }
#pragma unroll
            for (int i = 4; i < 8; i++) {
                ulonglong2 hq = hp[i];
                a0B = ffma2(w0[2 * i],     hq.x, a0B);
                a1B = ffma2(w1[2 * i],     hq.x, a1B);
                a0B = ffma2(w0[2 * i + 1], hq.y, a0B);
                a1B = ffma2(w1[2 * i + 1], hq.y, a1B);
            }
            float2 u0 = funpack2(fadd2(a0A, a0B));
            float2 u1 = funpack2(fadd2(a1A, a1B));
            s0B = u0.x + u0.y;
            s1B = u1.x + u1.y;
#pragma unroll
            for (int m = 1; m < 4; m <<= 1) {
                s0B += __shfl_xor_sync(0xffffffffu, s0B, m);
                s1B += __shfl_xor_sync(0xffffffffu, s1B, m);
            }
        }
        if (sender) {
            if (c == 0) {
                uint32_t raddr = peer_rsm_base +
                    ((2u + par) * (unsigned)RBUF + 2u * (unsigned)gg) * 4u;  // rsm[1][par]
                st_async_b64(raddr, fpack2(s0B, s1B), peer_mbB);
            }
        } else if (c < 2) {
            const int li = 2 * gg + c;               // local h index
            const unsigned nb = par ^ 1u;
            // ---- batch A: wait (flight covered by B compute), combine, tanh ----
            mbar_wait_parity(mbA, phase);
            {
                float pr = rsm[0][par][li];
                float hn = tanhf((c ? s1A : s0A) + pr + xvA);
                hsm[0][nb][HP * (li >> 5) + (li & 31)] = hn;
                outpA[(size_t)t * tstride] = hn;
                if (t + 1 < TT) xvA = xppA[(size_t)(t + 1) * tstride];
            }
            // ---- batch B ----
            mbar_wait_parity(mbB, phase);
            {
                float pr = rsm[1][par][li];
                float hn = tanhf((c ? s1B : s0B) + pr + xvB);
                hsm[1][nb][HP * (li >> 5) + (li & 31)] = hn;
                outpB[(size_t)t * tstride] = hn;
                if (t + 1 < TT) xvB = xppB[(size_t)(t + 1) * tstride];
            }
        }

        __syncthreads();   // new h halves visible CTA-wide; rsm[*][par] retired
    }
    CLUSTER_SYNC_();
}

// ---------------------------------------------------------------------------
// Launch
// ---------------------------------------------------------------------------
extern "C" void kernel_launch(void* const* d_in, const int* in_sizes, int n_in,
                              void* d_out, int out_size)
{
    const float* x    = (const float*)d_in[0];
    const float* Wih  = (const float*)d_in[1];
    const float* Whh  = (const float*)d_in[2];
    const float* b_ih = (const float*)d_in[3];
    const float* b_hh = (const float*)d_in[4];
    float* out = (float*)d_out;

    dim3 g1((TT * BB) / 128, HH / 128);
    xp_gemm_kernel<<<g1, 256>>>(x, Wih, b_ih, b_hh);

    // 32 clusters x 2 CTAs; each cluster interleaves 2 batches.
    rnn_scan_kernel<<<BB, 512>>>(Whh, out);
}

// round 14
// speedup vs baseline: 1.4007x; 1.4007x over previous
#include <cuda_runtime.h>
#include <math.h>
#include <stdint.h>

#define TT 2048
#define BB 64
#define KIN 256
#define HH 256

typedef unsigned long long ull;

// Scratch for precomputed input projection xp[t][b][h] (134 MB device global).
__device__ float g_xp[(size_t)TT * BB * HH];

// ---------------------------------------------------------------------------
// f32x2 helpers (Blackwell packed fp32 pipe)
// ---------------------------------------------------------------------------
__device__ __forceinline__ ull ffma2(ull a, ull b, ull c) {
    ull d;
    asm("fma.rn.f32x2 %0, %1, %2, %3;" : "=l"(d) : "l"(a), "l"(b), "l"(c));
    return d;
}
__device__ __forceinline__ ull fadd2(ull a, ull b) {
    ull d;
    asm("add.rn.f32x2 %0, %1, %2;" : "=l"(d) : "l"(a), "l"(b));
    return d;
}
__device__ __forceinline__ ull fdup2(float a) {
    ull d; unsigned u = __float_as_uint(a);
    asm("mov.b64 %0, {%1, %2};" : "=l"(d) : "r"(u), "r"(u));
    return d;
}
__device__ __forceinline__ ull fpack2(float a, float b) {
    ull d;
    asm("mov.b64 %0, {%1, %2};" : "=l"(d)
        : "r"(__float_as_uint(a)), "r"(__float_as_uint(b)));
    return d;
}
__device__ __forceinline__ float2 funpack2(ull a) {
    unsigned lo, hi;
    asm("mov.b64 {%0, %1}, %2;" : "=r"(lo), "=r"(hi) : "l"(a));
    return make_float2(__uint_as_float(lo), __uint_as_float(hi));
}
__device__ __forceinline__ uint32_t smem_u32(const void* p) {
    uint32_t a;
    asm("{ .reg .u64 t; cvta.to.shared.u64 t, %1; cvt.u32.u64 %0, t; }"
        : "=r"(a) : "l"(p));
    return a;
}
__device__ __forceinline__ uint32_t mapa_peer(uint32_t local, uint32_t peer) {
    uint32_t r;
    asm("mapa.shared::cluster.u32 %0, %1, %2;" : "=r"(r) : "r"(local), "r"(peer));
    return r;
}
__device__ __forceinline__ void st_async_b64(uint32_t raddr, ull v, uint32_t rbar) {
    asm volatile(
        "st.async.shared::cluster.mbarrier::complete_tx::bytes.b64 [%0], %1, [%2];"
        :: "r"(raddr), "l"(v), "r"(rbar) : "memory");
}
__device__ __forceinline__ void mbar_init(uint32_t addr, uint32_t cnt) {
    asm volatile("mbarrier.init.shared.b64 [%0], %1;" :: "r"(addr), "r"(cnt) : "memory");
}
__device__ __forceinline__ void mbar_expect_tx(uint32_t addr, uint32_t bytes) {
    asm volatile("mbarrier.arrive.expect_tx.shared.b64 _, [%0], %1;"
                 :: "r"(addr), "r"(bytes) : "memory");
}
__device__ __forceinline__ void mbar_wait_parity(uint32_t addr, uint32_t parity) {
    asm volatile(
        "{\n\t"
        ".reg .pred P;\n\t"
        "WL_%=:\n\t"
        "mbarrier.try_wait.parity.acquire.cluster.shared::cta.b64 P, [%0], %1, 0x989680;\n\t"
        "@!P bra WL_%=;\n\t"
        "}" :: "r"(addr), "r"(parity) : "memory");
}
#define CLUSTER_SYNC_() do { \
    asm volatile("barrier.cluster.arrive.aligned;" ::: "memory"); \
    asm volatile("barrier.cluster.wait.aligned;" ::: "memory"); \
} while (0)

// ---------------------------------------------------------------------------
// Kernel 1: xp[m][n] = x[m][:] . W_ih[n][:] + b_ih[n] + b_hh[n]
// f32x2 GEMM, 128x128 tile, BK=16, 256 threads, per-thread 8x8.
// NEW: A stored PRE-DUPLICATED in smem (zero fdup2 in the hot loop),
// double-buffered smem (one __syncthreads per ktile), register-prefetched LDG.
// smem layout (floats): As[2][16][264] (dup'd pairs, 2m), Bs[2][16][132].
// ---------------------------------------------------------------------------
#define AS_STR 264                    // floats per As k-row (128 dup pairs + pad)
#define BS_STR 132                    // floats per Bs k-row
#define AS_BUF (16 * AS_STR)          // 4224 floats per As buffer
#define BS_BUF (16 * BS_STR)          // 2112 floats per Bs buffer
#define GEMM_SMEM ((2 * AS_BUF + 2 * BS_BUF) * 4)   // 50688 bytes

__global__ __launch_bounds__(256, 2) void xp_gemm_kernel(
    const float* __restrict__ x,
    const float* __restrict__ Wih,
    const float* __restrict__ b_ih,
    const float* __restrict__ b_hh)
{
    extern __shared__ float sm[];
    float* Asb = sm;                       // [2][AS_BUF]
    float* Bsb = sm + 2 * AS_BUF;          // [2][BS_BUF]

    const int tid = threadIdx.x;
    const int m0 = blockIdx.x * 128;
    const int n0 = blockIdx.y * 128;
    const int ty = tid >> 4;
    const int tx = tid & 15;

    // Per-thread load slots: l in {0,1}; id = tid + 256*l covers 512 rows
    // (row 0..127 of A and of B), 4 floats each.
    const int row0 = tid >> 2;             // l=0 row
    const int row1 = (tid + 256) >> 2;     // l=1 row
    const int c4   = (tid & 3) * 4;

    ull acc[8][4];
#pragma unroll
    for (int i = 0; i < 8; i++)
#pragma unroll
        for (int p = 0; p < 4; p++) acc[i][p] = 0ull;

    float4 avr[2], bvr[2];

    // Prologue: LDG ktile 0, STS into buffer 0.
    avr[0] = *(const float4*)(x   + (size_t)(m0 + row0) * KIN + c4);
    avr[1] = *(const float4*)(x   + (size_t)(m0 + row1) * KIN + c4);
    bvr[0] = *(const float4*)(Wih + (size_t)(n0 + row0) * KIN + c4);
    bvr[1] = *(const float4*)(Wih + (size_t)(n0 + row1) * KIN + c4);
    {
        float* As = Asb;
        float* Bs = Bsb;
        const int rows[2] = { row0, row1 };
#pragma unroll
        for (int l = 0; l < 2; l++) {
            float av[4] = { avr[l].x, avr[l].y, avr[l].z, avr[l].w };
            float bv[4] = { bvr[l].x, bvr[l].y, bvr[l].z, bvr[l].w };
#pragma unroll
            for (int j = 0; j < 4; j++) {
                *(ull*)&As[(c4 + j) * AS_STR + 2 * rows[l]] = fdup2(av[j]);
                Bs[(c4 + j) * BS_STR + rows[l]] = bv[j];
            }
        }
    }
    __syncthreads();

    for (int kt = 0; kt < 16; kt++) {
        const int buf = kt & 1;
        // Prefetch next ktile from gmem into registers.
        if (kt < 15) {
            const int ko = (kt + 1) * 16;
            avr[0] = *(const float4*)(x   + (size_t)(m0 + row0) * KIN + ko + c4);
            avr[1] = *(const float4*)(x   + (size_t)(m0 + row1) * KIN + ko + c4);
            bvr[0] = *(const float4*)(Wih + (size_t)(n0 + row0) * KIN + ko + c4);
            bvr[1] = *(const float4*)(Wih + (size_t)(n0 + row1) * KIN + ko + c4);
        }

        // FMA over this ktile (A already duplicated: no MOVs in the loop).
        const float* As = Asb + buf * AS_BUF;
        const float* Bs = Bsb + buf * BS_BUF;
#pragma unroll
        for (int k = 0; k < 16; k++) {
            const ulonglong2* ap = (const ulonglong2*)&As[k * AS_STR + 16 * ty];
            ulonglong2 aq0 = ap[0];   // rows 0,1 dup'd
            ulonglong2 aq1 = ap[1];   // rows 2,3
            ulonglong2 aq2 = ap[2];   // rows 4,5
            ulonglong2 aq3 = ap[3];   // rows 6,7
            ulonglong2 bq0 = *(const ulonglong2*)&Bs[k * BS_STR + 8 * tx];
            ulonglong2 bq1 = *(const ulonglong2*)&Bs[k * BS_STR + 8 * tx + 4];
            ull ad[8] = { aq0.x, aq0.y, aq1.x, aq1.y, aq2.x, aq2.y, aq3.x, aq3.y };
            ull bp[4] = { bq0.x, bq0.y, bq1.x, bq1.y };
#pragma unroll
            for (int i = 0; i < 8; i++)
#pragma unroll
                for (int p = 0; p < 4; p++)
                    acc[i][p] = ffma2(ad[i], bp[p], acc[i][p]);
        }

        // Store next ktile to the other buffer; one sync per ktile.
        if (kt < 15) {
            float* Asn = Asb + (buf ^ 1) * AS_BUF;
            float* Bsn = Bsb + (buf ^ 1) * BS_BUF;
            const int rows[2] = { row0, row1 };
#pragma unroll
            for (int l = 0; l < 2; l++) {
                float av[4] = { avr[l].x, avr[l].y, avr[l].z, avr[l].w };
                float bv[4] = { bvr[l].x, bvr[l].y, bvr[l].z, bvr[l].w };
#pragma unroll
                for (int j = 0; j < 4; j++) {
                    *(ull*)&Asn[(c4 + j) * AS_STR + 2 * rows[l]] = fdup2(av[j]);
                    Bsn[(c4 + j) * BS_STR + rows[l]] = bv[j];
                }
            }
            __syncthreads();
        }
    }

    // Epilogue: fused bias, store.
    float bb[8];
#pragma unroll
    for (int j = 0; j < 8; j++) {
        int n = n0 + tx * 8 + j;
        bb[j] = b_ih[n] + b_hh[n];
    }
#pragma unroll
    for (int i = 0; i < 8; i++) {
        float* dst = g_xp + (size_t)(m0 + ty * 8 + i) * HH + n0 + tx * 8;
        float2 c0 = funpack2(acc[i][0]);
        float2 c1 = funpack2(acc[i][1]);
        float2 c2 = funpack2(acc[i][2]);
        float2 c3 = funpack2(acc[i][3]);
        float4 v0 = make_float4(c0.x + bb[0], c0.y + bb[1], c1.x + bb[2], c1.y + bb[3]);
        float4 v1 = make_float4(c2.x + bb[4], c2.y + bb[5], c3.x + bb[6], c3.y + bb[7]);
        *(float4*)dst       = v0;
        *(float4*)(dst + 4) = v1;
    }
}

// ---------------------------------------------------------------------------
// Kernel 2: serial recurrence — ROUND-12 PROVEN VERSION, unchanged.
// Cluster of 2 CTAs per batch (grid 128), partial-sum exchange:
//   senders = high warps 8-15 (arbiter priority), receivers = warps 0-7,
//   tanh split on c==0/c==1, dual f32x2 accumulators, c<2-only waits.
// Comm: 64 x 8 B st.async per step; two mbarriers alternated by t&1, phase
// (t>>1)&1; double-buffered recv + local h half; HP-padded conflict-free h.
// ---------------------------------------------------------------------------
#define HP   36                       // padded chunk stride (floats)
#define HBUF (4 * HP)                 // 144 floats per local-h buffer
#define RBUF 128                      // recv partials per buffer

__global__ __launch_bounds__(512, 1) __cluster_dims__(2, 1, 1)
void rnn_scan_kernel(const float* __restrict__ Whh, float* __restrict__ out)
{
    __shared__ __align__(16) float hsm[2][HBUF];   // own h half, double-buffered
    __shared__ __align__(16) float rsm[2][RBUF];   // recv partials, double-buffered
    __shared__ __align__(8)  ull   mbars[2];

    const int tid = threadIdx.x;
    const unsigned rank = blockIdx.x & 1u;
    const int batch = blockIdx.x >> 1;
    const int c  = tid & 3;                     // K sub-chunk / role lane
    const int gg = (tid >> 2) & 63;             // row-pair index within half
    const bool sender = (tid >= 256);           // warps 8-15: compute peer rows
    const int half_base = sender ? (int)((rank ^ 1u) * 128) : (int)(rank * 128);
    const int r0 = half_base + 2 * gg;          // target rows r0, r0+1
    const int k0 = (int)rank * 128 + 32 * c;    // own-K chunk

    const uint32_t mb0 = smem_u32(&mbars[0]);
    const uint32_t mb1 = smem_u32(&mbars[1]);
    const uint32_t rsm_addr = smem_u32(&rsm[0][0]);
    const uint32_t peer = rank ^ 1u;
    const uint32_t peer_mb0 = mapa_peer(mb0, peer);
    const uint32_t peer_mb1 = mapa_peer(mb1, peer);
    const uint32_t peer_rsm = mapa_peer(rsm_addr, peer);

    // Register-resident W: rows r0, r0+1 x K-chunk [k0, k0+32) as f32x2 pairs.
    ull w0[16], w1[16];
    {
        const ull* p0 = (const ull*)(Whh + (size_t)r0 * HH + k0);
        const ull* p1 = (const ull*)(Whh + (size_t)(r0 + 1) * HH + k0);
#pragma unroll
        for (int i = 0; i < 16; i++) { w0[i] = p0[i]; w1[i] = p1[i]; }
    }

    if (tid < HBUF) hsm[0][tid] = 0.0f;         // h_{-1} = 0 (own half)
    if (tid == 0) { mbar_init(mb0, 1); mbar_init(mb1, 1); }
    __syncthreads();
    CLUSTER_SYNC_();                             // peer mbars visible

    const size_t tstride = (size_t)BB * HH;
    // Receiver per-lane scalar row (c < 2): row r0 + c.
    const float* xpp  = g_xp + (size_t)batch * HH + r0 + c;
    float*       outp = out  + (size_t)batch * HH + r0 + c;

    float xv = 0.0f;
    if (!sender && c < 2) xv = *xpp;            // xp for t = 0

    for (int t = 0; t < TT; t++) {
        const unsigned par = (unsigned)t & 1u;
        const uint32_t mbar      = par ? mb1 : mb0;
        const uint32_t peer_mbar = par ? peer_mb1 : peer_mb0;
        const unsigned phase     = ((unsigned)t >> 1) & 1u;

        if (tid == 0) mbar_expect_tx(mbar, 512);   // 64 x 8 B from peer, step t

        // Partial dot over own-K chunk [32c, 32c+32): rows r0, r0+1.
        const ulonglong2* hp = (const ulonglong2*)&hsm[par][HP * c];
        ull a0A = 0ull, a1A = 0ull, a0B = 0ull, a1B = 0ull;
#pragma unroll
        for (int i = 0; i < 4; i++) {
            ulonglong2 hq = hp[i];
            a0A = ffma2(w0[2 * i],     hq.x, a0A);
            a1A = ffma2(w1[2 * i],     hq.x, a1A);
            a0A = ffma2(w0[2 * i + 1], hq.y, a0A);
            a1A = ffma2(w1[2 * i + 1], hq.y, a1A);
        }
#pragma unroll
        for (int i = 4; i < 8; i++) {
            ulonglong2 hq = hp[i];
            a0B = ffma2(w0[2 * i],     hq.x, a0B);
            a1B = ffma2(w1[2 * i],     hq.x, a1B);
            a0B = ffma2(w0[2 * i + 1], hq.y, a0B);
            a1B = ffma2(w1[2 * i + 1], hq.y, a1B);
        }
        float2 u0 = funpack2(fadd2(a0A, a0B));
        float2 u1 = funpack2(fadd2(a1A, a1B));
        float s0 = u0.x + u0.y;
        float s1 = u1.x + u1.y;
#pragma unroll
        for (int m = 1; m < 4; m <<= 1) {
            s0 += __shfl_xor_sync(0xffffffffu, s0, m);
            s1 += __shfl_xor_sync(0xffffffffu, s1, m);
        }

        if (sender) {
            // Send partials for peer's rows EARLY (hi-wid warps issue first).
            if (c == 0) {
                uint32_t raddr = peer_rsm + (par * (unsigned)RBUF + 2u * (unsigned)gg) * 4u;
                st_async_b64(raddr, fpack2(s0, s1), peer_mbar);
            }
        } else if (c < 2) {
            // Own rows: wait for peer partials of THIS step, combine, tanh.
            mbar_wait_parity(mbar, phase);
            const int li = 2 * gg + c;              // local h index
            float pr = rsm[par][li];
            float hn = tanhf((c ? s1 : s0) + pr + xv);
            const unsigned nb = par ^ 1u;
            hsm[nb][HP * (li >> 5) + (li & 31)] = hn;
            outp[(size_t)t * tstride] = hn;
            if (t + 1 < TT)
                xv = xpp[(size_t)(t + 1) * tstride];
        }

        __syncthreads();   // new own-h half visible CTA-wide; rsm[par] retired
    }
    CLUSTER_SYNC_();
}

// ---------------------------------------------------------------------------
// Launch
// ---------------------------------------------------------------------------
extern "C" void kernel_launch(void* const* d_in, const int* in_sizes, int n_in,
                              void* d_out, int out_size)
{
    const float* x    = (const float*)d_in[0];
    const float* Wih  = (const float*)d_in[1];
    const float* Whh  = (const float*)d_in[2];
    const float* b_ih = (const float*)d_in[3];
    const float* b_hh = (const float*)d_in[4];
    float* out = (float*)d_out;

    cudaFuncSetAttribute(xp_gemm_kernel,
                         cudaFuncAttributeMaxDynamicSharedMemorySize, GEMM_SMEM);
    dim3 g1((TT * BB) / 128, HH / 128);
    xp_gemm_kernel<<<g1, 256, GEMM_SMEM>>>(x, Wih, b_ih, b_hh);

    rnn_scan_kernel<<<2 * BB, 512>>>(Whh, out);
}